// round 17
// baseline (speedup 1.0000x reference)
#include <cuda_runtime.h>
#include <cuda_bf16.h>
#include <cuda_fp16.h>
#include <cstdint>

// Problem constants (GCN_60301340836134)
constexpr int N_NODES = 100000;
constexpr int N_EDGES = 1600000;
constexpr int D_IN    = 128;
constexpr int D_OUT   = 5;
constexpr int NOUT2   = 2 * D_OUT;          // 10 fused outputs (W_l | W_r)
constexpr int NPAIR   = NOUT2 / 2;          // 5 f32x2 pairs
constexpr int AGG_PAD = 8;                  // base rows: [b0..b4,pad..] f32
constexpr int YL_PADH = 8;                  // fp16 rows: 16B = one LDG.128

constexpr int K4      = D_IN / 4;           // 32 float4 per x row
constexpr int NPT     = 4;                  // nodes per thread (R12 config)
constexpr int NPB2    = 128;                // nodes per block (32 groups * 4)

// Scratch (no allocations allowed; device globals)
__device__ __align__(16) __half g_ylh [N_NODES * YL_PADH];  // x@W_l^T (fp16)
__device__ __align__(16) __half g_aggh[N_NODES * YL_PADH];  // fp16 sums+cnt
__device__ __align__(16) float  g_base[N_NODES * AGG_PAD];  // x@W_r^T + b_l

// ---------------------------------------------------------------------------
// PTX helpers
// ---------------------------------------------------------------------------
__device__ __forceinline__ void red_add_v4_f16x2(__half* addr, uint4 v) {
    asm volatile("red.global.add.noftz.v4.f16x2 [%0], {%1, %2, %3, %4};"
                 :: "l"(addr), "r"(v.x), "r"(v.y), "r"(v.z), "r"(v.w)
                 : "memory");
}
// packed fp32 pair FMA: d += a * b (elementwise on 2 floats) -> FFMA2
__device__ __forceinline__ void fma_f32x2(unsigned long long& d,
                                          unsigned long long a,
                                          unsigned long long b) {
    asm("fma.rn.f32x2 %0, %1, %2, %0;" : "+l"(d) : "l"(a), "l"(b));
}
__device__ __forceinline__ unsigned long long pack2(float lo, float hi) {
    unsigned long long r;
    asm("mov.b64 %0, {%1, %2};" : "=l"(r) : "f"(lo), "f"(hi));
    return r;
}
__device__ __forceinline__ void unpack2(unsigned long long v,
                                        float& lo, float& hi) {
    asm("mov.b64 {%0, %1}, %2;" : "=f"(lo), "=f"(hi) : "l"(v));
}

// ---------------------------------------------------------------------------
// Kernel 1: projection. R12/R16 structure (8 lanes per node-group, 4 nodes
// per thread, all 16 LDG.128 up front, 2 CTA/SM), but the inner product uses
// packed f32x2 FMA (FFMA2): 5 output-pairs, weights pre-packed in smem.
//   g_ylh[node]  = fp16(x[node] @ W_l^T), slots 5..7 = 0
//   g_base[node] = x[node] @ W_r^T + b_l
// Also zeroes g_aggh.
// ---------------------------------------------------------------------------
__global__ __launch_bounds__(256, 2) void proj_kernel(
    const float* __restrict__ x,
    const float* __restrict__ Wl,
    const float* __restrict__ bl,
    const float* __restrict__ Wr)
{
    // sW2[k*NPAIR + o2] = (W_out[2*o2][k], W_out[2*o2+1][k]),
    // where W_out[o] = (o < 5) ? Wl[o] : Wr[o-5].  Stride 5 pairs per k.
    __shared__ unsigned long long sW2[D_IN * NPAIR];   // 640 * 8B = 5 KB
    __shared__ float sb[D_OUT];

    const int tid   = threadIdx.x;
    const int g     = tid >> 3;        // group in block (0..31)
    const int c     = tid & 7;         // float4-chunk within tile (0..7)
    const int nbase = blockIdx.x * NPB2 + g * NPT;

    // zero g_aggh: 100000 uint4 rows over 782 blocks * 128
    if (tid < 128) {
        int zi = blockIdx.x * 128 + tid;
        if (zi < N_NODES)
            ((uint4*)g_aggh)[zi] = make_uint4(0u, 0u, 0u, 0u);
    }

    // stage packed weights (640 entries, strided loop)
    for (int i = tid; i < D_IN * NPAIR; i += 256) {
        int k  = i / NPAIR;
        int o2 = i - k * NPAIR;
        int oA = 2 * o2, oB = 2 * o2 + 1;
        float a = (oA < D_OUT) ? Wl[oA * D_IN + k] : Wr[(oA - D_OUT) * D_IN + k];
        float b = (oB < D_OUT) ? Wl[oB * D_IN + k] : Wr[(oB - D_OUT) * D_IN + k];
        sW2[i] = pack2(a, b);
    }
    if (tid < D_OUT) sb[tid] = bl[tid];

    const float4* x4 = (const float4*)x;

    // ---- phase 1: issue ALL 16 coalesced LDG.128 back-to-back ----
    float4 xv[NPT][4];
#pragma unroll
    for (int j = 0; j < NPT; j++) {
        int node = nbase + j;
        int nc   = (node < N_NODES) ? node : 0;   // clamp (tail block)
        const float4* row = x4 + (size_t)nc * K4 + c;
#pragma unroll
        for (int t = 0; t < 4; t++)
            xv[j][t] = row[t * 8];
    }

    __syncthreads();   // weights visible (overlaps with LDGs in flight)

    // ---- phase 2: packed-pair FMA ----
    unsigned long long acc2[NPT][NPAIR];
#pragma unroll
    for (int j = 0; j < NPT; j++)
#pragma unroll
        for (int p = 0; p < NPAIR; p++) acc2[j][p] = 0ull;

#pragma unroll
    for (int t = 0; t < 4; t++) {
        const int k0 = (t * 8 + c) * 4;      // scalar k base for this chunk
#pragma unroll
        for (int kk = 0; kk < 4; kk++) {
            unsigned long long w0 = sW2[(k0 + kk) * NPAIR + 0];
            unsigned long long w1 = sW2[(k0 + kk) * NPAIR + 1];
            unsigned long long w2 = sW2[(k0 + kk) * NPAIR + 2];
            unsigned long long w3 = sW2[(k0 + kk) * NPAIR + 3];
            unsigned long long w4 = sW2[(k0 + kk) * NPAIR + 4];
#pragma unroll
            for (int j = 0; j < NPT; j++) {
                float xs = (kk == 0) ? xv[j][t].x
                         : (kk == 1) ? xv[j][t].y
                         : (kk == 2) ? xv[j][t].z
                                     : xv[j][t].w;
                unsigned long long xx = pack2(xs, xs);
                fma_f32x2(acc2[j][0], xx, w0);
                fma_f32x2(acc2[j][1], xx, w1);
                fma_f32x2(acc2[j][2], xx, w2);
                fma_f32x2(acc2[j][3], xx, w3);
                fma_f32x2(acc2[j][4], xx, w4);
            }
        }
    }

    // unpack + reduce each (node, o) over the 8-lane group
#pragma unroll
    for (int j = 0; j < NPT; j++) {
        float acc[NOUT2];
#pragma unroll
        for (int p = 0; p < NPAIR; p++)
            unpack2(acc2[j][p], acc[2 * p], acc[2 * p + 1]);
#pragma unroll
        for (int o = 0; o < NOUT2; o++) {
            acc[o] += __shfl_xor_sync(0xFFFFFFFFu, acc[o], 4);
            acc[o] += __shfl_xor_sync(0xFFFFFFFFu, acc[o], 2);
            acc[o] += __shfl_xor_sync(0xFFFFFFFFu, acc[o], 1);
        }

        if (c == 0) {
            int node = nbase + j;
            if (node < N_NODES) {
                __half2 h01 = __floats2half2_rn(acc[0], acc[1]);
                __half2 h23 = __floats2half2_rn(acc[2], acc[3]);
                __half2 h4z = __floats2half2_rn(acc[4], 0.f);
                uint4 u;
                u.x = *(unsigned*)&h01;
                u.y = *(unsigned*)&h23;
                u.z = *(unsigned*)&h4z;
                u.w = 0u;
                ((uint4*)(g_ylh + (size_t)node * YL_PADH))[0] = u;

                float4* bp = (float4*)(g_base + (size_t)node * AGG_PAD);
                bp[0] = make_float4(acc[5] + sb[0], acc[6] + sb[1],
                                    acc[7] + sb[2], acc[8] + sb[3]);
                bp[1] = make_float4(acc[9] + sb[4], 0.f, 0.f, 0.f);
            }
        }
    }
}

// ---------------------------------------------------------------------------
// Kernel 2: edge scatter. 4 edges per thread (int4 index loads).
// Per edge: ONE 16B gather + ONE v4.f16x2 RED (8 fp16: y0..y4 + count).
// ---------------------------------------------------------------------------
__global__ __launch_bounds__(256) void scatter_kernel(
    const int* __restrict__ src,
    const int* __restrict__ dst)
{
    constexpr int E4 = N_EDGES / 4;  // 400000
    int t = blockIdx.x * blockDim.x + threadIdx.x;
    if (t >= E4) return;

    int4 s4 = ((const int4*)src)[t];
    int4 d4 = ((const int4*)dst)[t];

    int ss[4] = {s4.x, s4.y, s4.z, s4.w};
    int dd[4] = {d4.x, d4.y, d4.z, d4.w};

    uint4 u[4];
#pragma unroll
    for (int k = 0; k < 4; k++) {
        unsigned s = (unsigned)ss[k];
        if (s >= (unsigned)N_NODES) s = 0;  // defensive
        u[k] = ((const uint4*)(g_ylh + (size_t)s * YL_PADH))[0];
    }

#pragma unroll
    for (int k = 0; k < 4; k++) {
        unsigned d = (unsigned)dd[k];
        if (d >= (unsigned)N_NODES) continue;

        // slot5 (high half of .z) <- 1.0h (0x3C00): degree count
        uint4 v = u[k];
        v.z = (v.z & 0x0000FFFFu) | 0x3C000000u;
        red_add_v4_f16x2(g_aggh + (size_t)d * YL_PADH, v);
    }
}

// ---------------------------------------------------------------------------
// Kernel 3: finalize, fully coalesced.
//   out[n][o] = base[n][o] + f32(aggh[n][o]) / max(f32(cnt), 1)
// ---------------------------------------------------------------------------
__global__ __launch_bounds__(256) void finalize_kernel(float* __restrict__ out)
{
    __shared__ float s_out[256 * D_OUT];  // 1280 floats = 320 float4

    int tid  = threadIdx.x;
    int node = blockIdx.x * 256 + tid;

    if (node < N_NODES) {
        uint4 au = ((const uint4*)(g_aggh + (size_t)node * YL_PADH))[0];
        const float4* bp = (const float4*)(g_base + (size_t)node * AGG_PAD);
        float4 b0 = bp[0], b1 = bp[1];

        float2 a01 = __half22float2(*(__half2*)&au.x);
        float2 a23 = __half22float2(*(__half2*)&au.y);
        float2 a4c = __half22float2(*(__half2*)&au.z);

        float inv = 1.0f / fmaxf(a4c.y, 1.0f);   // count in slot 5

        s_out[tid * D_OUT + 0] = b0.x + a01.x * inv;
        s_out[tid * D_OUT + 1] = b0.y + a01.y * inv;
        s_out[tid * D_OUT + 2] = b0.z + a23.x * inv;
        s_out[tid * D_OUT + 3] = b0.w + a23.y * inv;
        s_out[tid * D_OUT + 4] = b1.x + a4c.x * inv;
    }
    __syncthreads();

    int base_f  = blockIdx.x * 256 * D_OUT;
    int total_f = N_NODES * D_OUT;
#pragma unroll
    for (int j = tid; j < 320; j += 256) {
        int f = base_f + j * 4;
        if (f + 3 < total_f) {
            ((float4*)out)[base_f / 4 + j] = ((const float4*)s_out)[j];
        } else if (f < total_f) {
            for (int q = 0; q < total_f - f; q++)
                out[f + q] = s_out[j * 4 + q];
        }
    }
}

// ---------------------------------------------------------------------------
// Launch
// Inputs (metadata order): x [N*128 f32], edge_index [2*E int32 on device],
//                          W_l [5*128 f32], b_l [5 f32], W_r [5*128 f32]
// Output: [N*5 f32]
// ---------------------------------------------------------------------------
extern "C" void kernel_launch(void* const* d_in, const int* in_sizes, int n_in,
                              void* d_out, int out_size)
{
    const float* x    = (const float*)d_in[0];
    const int*   eidx = (const int*)d_in[1];
    const float* Wl   = (const float*)d_in[2];
    const float* bl   = (const float*)d_in[3];
    const float* Wr   = (const float*)d_in[4];
    float*       out  = (float*)d_out;

    const int* src = eidx;            // edge_index[0]
    const int* dst = eidx + N_EDGES;  // edge_index[1]

    {
        int blocks = (N_NODES + NPB2 - 1) / NPB2;   // 782; also zeroes g_aggh
        proj_kernel<<<blocks, 256>>>(x, Wl, bl, Wr);
    }
    {
        constexpr int E4 = N_EDGES / 4;
        scatter_kernel<<<(E4 + 255) / 256, 256>>>(src, dst);
    }
    {
        int blocks = (N_NODES + 255) / 256;
        finalize_kernel<<<blocks, 256>>>(out);
    }
}